// round 3
// baseline (speedup 1.0000x reference)
#include <cuda_runtime.h>
#include <cuda_bf16.h>

// ---------------------------------------------------------------------------
// AliasFreeActivation: bias -> up2x(12x12 FIR, pad10, gain4) -> lrelu*sqrt2,
// clamp(+-256) -> 12x12 FIR down2x.
// Input  [8,128,128,128] f32, mid [.,264,264], output [8,128,127,127] f32.
//
// Fully fused, one block = 32x64 output tile of one plane.
// Polyphase up-conv: mid(my,mx) uses 6x6 taps of fu with parity (my&1, mx&1).
// ---------------------------------------------------------------------------

#define H      128
#define W      128
#define OHW    127
#define TY     32
#define TX     64
#define MIDH   74          // 2*TY+10
#define MIDW   138         // 2*TX+10
#define MSTR   148         // mid smem stride (words), 16B-aligned rows
#define INH    43          // TY+11
#define INW    79          // >= TX+11 (=75) + phase-B chunk overrun (needs 78)
#define NTHREADS 256

#define S_IN_OFF   0
#define S_MID_OFF  3400                  // INH*INW=3397 padded to /4
#define S_FU_OFF   (S_MID_OFF + MIDH*MSTR)   // 3400+10952 = 14352
#define S_FD_OFF   (S_FU_OFF + 144)          // 14496
#define SMEM_FLOATS (S_FD_OFF + 144)         // 14640 -> 58560 bytes

__global__ __launch_bounds__(NTHREADS)
void afa_fused_kernel(const float* __restrict__ in,
                      const float* __restrict__ bias,
                      const float* __restrict__ fu,
                      const float* __restrict__ fd,
                      float* __restrict__ out)
{
    extern __shared__ float sm[];
    float* s_in  = sm + S_IN_OFF;
    float* s_mid = sm + S_MID_OFF;
    float* s_fu  = sm + S_FU_OFF;
    float* s_fd  = sm + S_FD_OFF;

    const int tid   = threadIdx.x;
    const int b     = blockIdx.x;
    const int plane = b >> 3;          // n*128 + c
    const int t8    = b & 7;
    const int ty    = t8 >> 1;         // 0..3
    const int tx    = t8 & 1;          // 0..1
    const int oy0   = ty * TY;
    const int ox0   = tx * TX;
    const int iy0   = oy0 - 5;
    const int ix0   = ox0 - 5;

    const float bv = __ldg(&bias[plane & 127]);
    const float* __restrict__ inp = in + (size_t)plane * (H * W);

    // ---- filters into smem (fu pre-scaled by UP*UP = 4) ----
    for (int i = tid; i < 144; i += NTHREADS) {
        s_fu[i] = __ldg(&fu[i]) * 4.0f;
        s_fd[i] = __ldg(&fd[i]);
    }
    // ---- input tile (+bias, zero pad OOB) ----
    for (int i = tid; i < INH * INW; i += NTHREADS) {
        const int r  = i / INW;
        const int cc = i - r * INW;
        const int gy = iy0 + r;
        const int gx = ix0 + cc;
        float v = 0.0f;
        if ((unsigned)gy < (unsigned)H && (unsigned)gx < (unsigned)W)
            v = __ldg(&inp[gy * W + gx]) + bv;
        s_in[i] = v;
    }
    __syncthreads();

    // ---- Phase B: polyphase up-conv + activation into s_mid ----
    // job = (mid row my, 16-wide column chunk). 9 chunks cover 138 (padded 144).
    const float SQ2 = 1.41421356237309515f;
    for (int job = tid; job < MIDH * 9; job += NTHREADS) {
        const int my = job / 9;
        const int c0 = (job - my * 9) << 4;
        const int py = my & 1;
        const int ql = my >> 1;
        const int bic = c0 >> 1;

        float acc[16];
        #pragma unroll
        for (int u = 0; u < 16; u++) acc[u] = 0.0f;

        #pragma unroll 1
        for (int t = 0; t < 6; t++) {
            const float* row = s_in + (ql + t + py) * INW + bic;
            float xv[14];
            #pragma unroll
            for (int j = 0; j < 14; j++) xv[j] = row[j];

            const float4* fr4 = (const float4*)(s_fu + (2 * t + py) * 12);
            float f[12];
            #pragma unroll
            for (int q = 0; q < 3; q++) {
                float4 v4 = fr4[q];
                f[4 * q + 0] = v4.x; f[4 * q + 1] = v4.y;
                f[4 * q + 2] = v4.z; f[4 * q + 3] = v4.w;
            }
            #pragma unroll
            for (int u = 0; u < 16; u++) {
                const int off = (u >> 1) + (u & 1);
                const int pxu = u & 1;
                #pragma unroll
                for (int s = 0; s < 6; s++)
                    acc[u] = fmaf(xv[off + s], f[2 * s + pxu], acc[u]);
            }
        }
        // activation: v*= (already x4 via filter); lrelu * sqrt2; clamp +-256
        #pragma unroll
        for (int u = 0; u < 16; u++) {
            float v = acc[u];
            v = fmaxf(v, 0.2f * v) * SQ2;
            v = fminf(fmaxf(v, -256.0f), 256.0f);
            acc[u] = v;
        }
        float4* ms4 = (float4*)(s_mid + my * MSTR + c0);
        #pragma unroll
        for (int q = 0; q < 4; q++)
            ms4[q] = make_float4(acc[4 * q], acc[4 * q + 1],
                                 acc[4 * q + 2], acc[4 * q + 3]);
    }
    __syncthreads();

    // ---- Phase C: 12x12 down-conv, stride 2 ----
    // thread -> (output row oyl, 8-wide column run)
    const int oyl = tid >> 3;            // 0..31
    const int c0  = (tid & 7) << 3;      // 0,8,...,56

    float acc[8];
    #pragma unroll
    for (int r = 0; r < 8; r++) acc[r] = 0.0f;

    #pragma unroll 1
    for (int ky = 0; ky < 12; ky++) {
        const float* mrow = s_mid + (2 * oyl + ky) * MSTR + 2 * c0;
        float m[26];
        const float4* m4 = (const float4*)mrow;
        #pragma unroll
        for (int q = 0; q < 6; q++) {
            float4 v4 = m4[q];
            m[4 * q + 0] = v4.x; m[4 * q + 1] = v4.y;
            m[4 * q + 2] = v4.z; m[4 * q + 3] = v4.w;
        }
        m[24] = mrow[24];
        m[25] = mrow[25];

        const float4* fr4 = (const float4*)(s_fd + ky * 12);
        float f[12];
        #pragma unroll
        for (int q = 0; q < 3; q++) {
            float4 v4 = fr4[q];
            f[4 * q + 0] = v4.x; f[4 * q + 1] = v4.y;
            f[4 * q + 2] = v4.z; f[4 * q + 3] = v4.w;
        }
        #pragma unroll
        for (int kx = 0; kx < 12; kx++)
            #pragma unroll
            for (int r = 0; r < 8; r++)
                acc[r] = fmaf(f[kx], m[2 * r + kx], acc[r]);
    }

    const int gy = oy0 + oyl;
    if (gy < OHW) {
        const int gx0 = ox0 + c0;
        float* op = out + (size_t)plane * (OHW * OHW) + gy * OHW + gx0;
        #pragma unroll
        for (int r = 0; r < 8; r++)
            if (gx0 + r < OHW) op[r] = acc[r];
    }
}

extern "C" void kernel_launch(void* const* d_in, const int* in_sizes, int n_in,
                              void* d_out, int out_size)
{
    const float* in   = (const float*)d_in[0];
    const float* bias = (const float*)d_in[1];
    const float* fu   = (const float*)d_in[2];
    const float* fd   = (const float*)d_in[3];
    float* out        = (float*)d_out;

    const size_t smem = SMEM_FLOATS * sizeof(float);   // 58560 B
    cudaFuncSetAttribute(afa_fused_kernel,
                         cudaFuncAttributeMaxDynamicSharedMemorySize, (int)smem);

    const int nblocks = 1024 * 8;   // (N*C) planes * (4 y-tiles * 2 x-tiles)
    afa_fused_kernel<<<nblocks, NTHREADS, smem>>>(in, bias, fu, fd, out);
}

// round 6
// speedup vs baseline: 1.3548x; 1.3548x over previous
#include <cuda_runtime.h>
#include <cuda_bf16.h>

// ---------------------------------------------------------------------------
// AliasFreeActivation: bias -> up2x(12x12 FIR, pad10, gain4) -> lrelu*sqrt2,
// clamp(+-256) -> 12x12 FIR down2x.
// Input [8,128,128,128] f32 -> mid [264,264] -> out [8,128,127,127] f32.
//
// Block = 32x64 output tile of one plane. Mid stored parity-split as
// interleaved (even,odd) float2 pairs; all inner FMAs are packed fma.rn.f32x2.
// ---------------------------------------------------------------------------

#define H      128
#define W      128
#define OHW    127
#define TY     32
#define TX     64
#define MIDH   74          // 2*TY+10
#define MSTR2  73          // mid row stride in float2 pairs (73%16==9, conflict-free)
#define INH    43
#define INW    79          // 79%32==15, coprime -> conflict-free row-strided reads
#define NTHREADS 256

#define S_IN_OFF   0
#define S_MID_OFF  3400                      // floats; 3400*4=13600, 16B aligned
#define S_FU_OFF   (S_MID_OFF + MIDH*MSTR2*2)   // 3400+10804 = 14204 (16B aligned)
#define S_FD_OFF   (S_FU_OFF + 144)             // 14348 (16B aligned)
#define SMEM_FLOATS (S_FD_OFF + 144)            // 14492 -> 57968 bytes

typedef unsigned long long u64;

__device__ __forceinline__ u64 ffma2(u64 a, u64 b, u64 c) {
    u64 d;
    asm("fma.rn.f32x2 %0, %1, %2, %3;" : "=l"(d) : "l"(a), "l"(b), "l"(c));
    return d;
}
__device__ __forceinline__ u64 pack2(float lo, float hi) {
    u64 d;
    asm("mov.b64 %0, {%1, %2};" : "=l"(d) : "f"(lo), "f"(hi));
    return d;
}
__device__ __forceinline__ float2 unpack2(u64 d) {
    float2 f;
    asm("mov.b64 {%0, %1}, %2;" : "=f"(f.x), "=f"(f.y) : "l"(d));
    return f;
}

__global__ __launch_bounds__(NTHREADS)
void afa_fused_kernel(const float* __restrict__ in,
                      const float* __restrict__ bias,
                      const float* __restrict__ fu,
                      const float* __restrict__ fd,
                      float* __restrict__ out)
{
    extern __shared__ float sm[];
    float* s_in  = sm + S_IN_OFF;
    float* s_mid = sm + S_MID_OFF;   // float2 pairs, stride MSTR2 pairs per row
    float* s_fu  = sm + S_FU_OFF;
    float* s_fd  = sm + S_FD_OFF;

    const int tid   = threadIdx.x;
    const int b     = blockIdx.x;
    const int plane = b >> 3;
    const int t8    = b & 7;
    const int oy0   = (t8 >> 1) * TY;
    const int ox0   = (t8 & 1) * TX;
    const int iy0   = oy0 - 5;
    const int ix0   = ox0 - 5;

    const float bv = __ldg(&bias[plane & 127]);
    const float* __restrict__ inp = in + (size_t)plane * (H * W);

    // ---- Phase A: filters (fu prescaled by 4) + input tile (+bias, 0-pad) --
    for (int i = tid; i < 144; i += NTHREADS) {
        s_fu[i] = __ldg(&fu[i]) * 4.0f;
        s_fd[i] = __ldg(&fd[i]);
    }
    for (int i = tid; i < INH * INW; i += NTHREADS) {
        const int r  = i / INW;
        const int cc = i - r * INW;
        const int gy = iy0 + r;
        const int gx = ix0 + cc;
        float v = 0.0f;
        if ((unsigned)gy < (unsigned)H && (unsigned)gx < (unsigned)W)
            v = __ldg(&inp[gy * W + gx]) + bv;
        s_in[i] = v;
    }
    __syncthreads();

    // ---- Phase B: polyphase up-conv (packed E,O) + activation -> MID2 ------
    // job = chunk*74 + my : consecutive lanes -> consecutive mid rows.
    // Each job computes 8 (E,O) pairs = 16 mid columns.
    const float SQ2 = 1.41421356237309515f;
    for (int job = tid; job < 74 * 9; job += NTHREADS) {
        const int chunk = job / 74;
        const int my    = job - chunk * 74;
        const int j0    = chunk * 8;          // pair-column base (<=64)
        const int py    = my & 1;
        const int qy    = my >> 1;

        u64 acc[8];
        #pragma unroll
        for (int jj = 0; jj < 8; jj++) acc[jj] = 0ull;

        #pragma unroll
        for (int t = 0; t < 6; t++) {
            const float* row = s_in + (qy + py + t) * INW + j0;
            float xv[14];
            #pragma unroll
            for (int j = 0; j < 14; j++) xv[j] = row[j];

            // filter row (2t+py): pairs (fu[2s],fu[2s+1]) via two 16B loads
            const u64* fu2 = (const u64*)(s_fu + (2 * t + py) * 12);
            u64 f0 = fu2[0], f1 = fu2[1], f2v = fu2[2],
                f3 = fu2[3], f4 = fu2[4], f5 = fu2[5];

            u64 pr[13];
            #pragma unroll
            for (int a = 0; a < 13; a++) pr[a] = pack2(xv[a], xv[a + 1]);

            #pragma unroll
            for (int jj = 0; jj < 8; jj++) {
                acc[jj] = ffma2(pr[jj + 0], f0, acc[jj]);
                acc[jj] = ffma2(pr[jj + 1], f1, acc[jj]);
                acc[jj] = ffma2(pr[jj + 2], f2v, acc[jj]);
                acc[jj] = ffma2(pr[jj + 3], f3, acc[jj]);
                acc[jj] = ffma2(pr[jj + 4], f4, acc[jj]);
                acc[jj] = ffma2(pr[jj + 5], f5, acc[jj]);
            }
        }
        // activation + store pair (E,O)
        float2* mrow = (float2*)s_mid + my * MSTR2 + j0;
        #pragma unroll
        for (int jj = 0; jj < 8; jj++) {
            float2 v = unpack2(acc[jj]);
            v.x = fminf(fmaxf(fmaxf(v.x, 0.2f * v.x) * SQ2, -256.0f), 256.0f);
            v.y = fminf(fmaxf(fmaxf(v.y, 0.2f * v.y) * SQ2, -256.0f), 256.0f);
            mrow[jj] = v;
        }
    }
    __syncthreads();

    // ---- Phase C: 12x12 down-conv stride 2, packed over (E,O) --------------
    // warp w: row-group rg=w>>1 (8 consecutive out rows), col half (w&1)*32.
    // lane = column. Each mid row feeds up to 6 accumulators.
    {
        const int wrp  = tid >> 5;
        const int lane = tid & 31;
        const int rg   = wrp >> 1;
        const int c    = ((wrp & 1) << 5) + lane;   // 0..63
        const int mbase = rg << 4;                  // 16*rg

        u64 acc[8];
        #pragma unroll
        for (int r = 0; r < 8; r++) acc[r] = 0ull;

        #pragma unroll
        for (int mm = 0; mm < 26; mm++) {
            const u64* mrow = (const u64*)((float2*)s_mid + (mbase + mm) * MSTR2 + c);
            u64 md[6];
            #pragma unroll
            for (int s = 0; s < 6; s++) md[s] = mrow[s];

            const int rlo = (mm >= 11) ? ((mm - 10) >> 1) : 0;
            const int rhi = (mm >> 1) < 7 ? (mm >> 1) : 7;
            #pragma unroll
            for (int r = 0; r < 8; r++) {
                if (r < rlo || r > rhi) continue;       // folds at compile time
                const int ky = mm - 2 * r;
                const u64* fd2 = (const u64*)(s_fd + ky * 12);
                acc[r] = ffma2(md[0], fd2[0], acc[r]);
                acc[r] = ffma2(md[1], fd2[1], acc[r]);
                acc[r] = ffma2(md[2], fd2[2], acc[r]);
                acc[r] = ffma2(md[3], fd2[3], acc[r]);
                acc[r] = ffma2(md[4], fd2[4], acc[r]);
                acc[r] = ffma2(md[5], fd2[5], acc[r]);
            }
        }

        const int gx = ox0 + c;
        if (gx < OHW) {
            float* op = out + (size_t)plane * (OHW * OHW) + gx;
            #pragma unroll
            for (int r = 0; r < 8; r++) {
                const int gy = oy0 + (rg << 3) + r;
                if (gy < OHW) {
                    float2 v = unpack2(acc[r]);
                    op[gy * OHW] = v.x + v.y;
                }
            }
        }
    }
}

extern "C" void kernel_launch(void* const* d_in, const int* in_sizes, int n_in,
                              void* d_out, int out_size)
{
    const float* in   = (const float*)d_in[0];
    const float* bias = (const float*)d_in[1];
    const float* fu   = (const float*)d_in[2];
    const float* fd   = (const float*)d_in[3];
    float* out        = (float*)d_out;

    const size_t smem = SMEM_FLOATS * sizeof(float);   // 57968 B
    cudaFuncSetAttribute(afa_fused_kernel,
                         cudaFuncAttributeMaxDynamicSharedMemorySize, (int)smem);

    const int nblocks = 1024 * 8;
    afa_fused_kernel<<<nblocks, NTHREADS, smem>>>(in, bias, fu, fd, out);
}

// round 7
// speedup vs baseline: 1.4708x; 1.0856x over previous
#include <cuda_runtime.h>
#include <cuda_bf16.h>

// ---------------------------------------------------------------------------
// AliasFreeActivation: bias -> up2x(12x12 FIR, pad10, gain4) -> lrelu*sqrt2,
// clamp(+-256) -> 12x12 FIR down2x.
// Input [8,128,128,128] f32 -> mid [264,264] -> out [8,128,127,127] f32.
//
// Block = 32x64 output tile of one plane, 384 threads.
// Input stored twice (sA = row, sB = row shifted 1) so all overlapping pairs
// are aligned LDS.64. Mid stored parity-split (E,O) float2. All inner FMAs
// are packed fma.rn.f32x2. Filter rows loaded as LDS.128 (ulonglong2).
// ---------------------------------------------------------------------------

#define H      128
#define W      128
#define OHW    127
#define TY     32
#define TX     64
#define MIDH   74          // 2*TY+10
#define MSTR2  73          // mid row stride in float2 pairs
#define INH    43
#define INW    78          // input row width (cols 0..77 needed)
#define NTHREADS 384

#define S_SA_OFF   0
#define S_SB_OFF   (INH*INW)                 // 3354
#define S_MID_OFF  (2*INH*INW)               // 6708  (byte 26832, 16B aligned)
#define S_FU_OFF   (S_MID_OFF + MIDH*MSTR2*2)   // 6708+10804 = 17512 (16B aligned)
#define S_FD_OFF   (S_FU_OFF + 144)             // 17656 (16B aligned)
#define SMEM_FLOATS (S_FD_OFF + 144)            // 17800 -> 71200 bytes

typedef unsigned long long u64;

__device__ __forceinline__ u64 ffma2(u64 a, u64 b, u64 c) {
    u64 d;
    asm("fma.rn.f32x2 %0, %1, %2, %3;" : "=l"(d) : "l"(a), "l"(b), "l"(c));
    return d;
}
__device__ __forceinline__ float2 unpack2(u64 d) {
    float2 f;
    asm("mov.b64 {%0, %1}, %2;" : "=f"(f.x), "=f"(f.y) : "l"(d));
    return f;
}

__global__ __launch_bounds__(NTHREADS, 2)
void afa_fused_kernel(const float* __restrict__ in,
                      const float* __restrict__ bias,
                      const float* __restrict__ fu,
                      const float* __restrict__ fd,
                      float* __restrict__ out)
{
    extern __shared__ float sm[];
    float* s_sa  = sm + S_SA_OFF;
    float* s_sb  = sm + S_SB_OFF;
    float* s_mid = sm + S_MID_OFF;   // float2 pairs, stride MSTR2 per row
    float* s_fu  = sm + S_FU_OFF;
    float* s_fd  = sm + S_FD_OFF;

    const int tid   = threadIdx.x;
    const int b     = blockIdx.x;
    const int plane = b >> 3;
    const int t8    = b & 7;
    const int oy0   = (t8 >> 1) * TY;
    const int ox0   = (t8 & 1) * TX;
    const int iy0   = oy0 - 5;
    const int ix0   = ox0 - 5;

    const float bv = __ldg(&bias[plane & 127]);
    const float* __restrict__ inp = in + (size_t)plane * (H * W);

    // ---- Phase A: filters (fu prescaled by 4) + dual input copies ----------
    for (int i = tid; i < 144; i += NTHREADS) {
        s_fu[i] = __ldg(&fu[i]) * 4.0f;
        s_fd[i] = __ldg(&fd[i]);
    }
    for (int i = tid; i < INH * INW; i += NTHREADS) {
        const int r  = i / INW;
        const int cc = i - r * INW;
        const int gy = iy0 + r;
        const int gx = ix0 + cc;
        float v = 0.0f;
        if ((unsigned)gy < (unsigned)H && (unsigned)gx < (unsigned)W)
            v = __ldg(&inp[gy * W + gx]) + bv;
        s_sa[i] = v;                       // sA[w] = x[w]
        if (cc > 0) s_sb[i - 1] = v;       // sB[w] = x[w+1]
    }
    __syncthreads();

    // ---- Phase B: polyphase up-conv (packed E,O) + activation -> MID2 ------
    // job = chunk*74 + my. Each job: 8 (E,O) pairs = 16 mid columns.
    const float SQ2 = 1.41421356237309515f;
    for (int job = tid; job < 74 * 9; job += NTHREADS) {
        const int chunk = job / 74;
        const int my    = job - chunk * 74;
        const int j0    = chunk * 8;          // word/pair-col base (even)
        const int py    = my & 1;
        const int qy    = my >> 1;

        u64 acc[8];
        #pragma unroll
        for (int jj = 0; jj < 8; jj++) acc[jj] = 0ull;

        #pragma unroll
        for (int t = 0; t < 6; t++) {
            const int rowoff = (qy + py + t) * INW + j0;   // even
            const u64* pa = (const u64*)(s_sa + rowoff);   // (x[a],x[a+1]), a even
            const u64* pb = (const u64*)(s_sb + rowoff);   // (x[a],x[a+1]), a odd
            u64 pe[7], po[6];
            #pragma unroll
            for (int m = 0; m < 7; m++) pe[m] = pa[m];
            #pragma unroll
            for (int m = 0; m < 6; m++) po[m] = pb[m];

            const ulonglong2* fq = (const ulonglong2*)(s_fu + (2 * t + py) * 12);
            ulonglong2 f01 = fq[0], f23 = fq[1], f45 = fq[2];
            const u64 f0 = f01.x, f1 = f01.y, f2v = f23.x,
                      f3 = f23.y, f4 = f45.x, f5 = f45.y;

            #pragma unroll
            for (int jj = 0; jj < 8; jj++) {
                // pr[a] = (a even) ? pe[a/2] : po[a/2],  a = jj+s
                #define PR(a) (((a) & 1) ? po[(a) >> 1] : pe[(a) >> 1])
                acc[jj] = ffma2(PR(jj + 0), f0, acc[jj]);
                acc[jj] = ffma2(PR(jj + 1), f1, acc[jj]);
                acc[jj] = ffma2(PR(jj + 2), f2v, acc[jj]);
                acc[jj] = ffma2(PR(jj + 3), f3, acc[jj]);
                acc[jj] = ffma2(PR(jj + 4), f4, acc[jj]);
                acc[jj] = ffma2(PR(jj + 5), f5, acc[jj]);
                #undef PR
            }
        }
        // activation + store pair (E,O)
        float2* mrow = (float2*)s_mid + my * MSTR2 + j0;
        #pragma unroll
        for (int jj = 0; jj < 8; jj++) {
            float2 v = unpack2(acc[jj]);
            v.x = fminf(fmaxf(fmaxf(v.x, 0.2f * v.x) * SQ2, -256.0f), 256.0f);
            v.y = fminf(fmaxf(fmaxf(v.y, 0.2f * v.y) * SQ2, -256.0f), 256.0f);
            mrow[jj] = v;
        }
    }
    __syncthreads();

    // ---- Phase C: 12x12 down-conv stride 2, packed over (E,O) --------------
    // 12 warps: warp w -> row group rg=w>>1 (6 out rows), col half (w&1)*32.
    // lane = column. Each mid row feeds up to 6 accumulators.
    {
        const int wrp  = tid >> 5;
        const int lane = tid & 31;
        const int rg   = wrp >> 1;                  // 0..5
        const int c    = ((wrp & 1) << 5) + lane;   // 0..63
        const int mbase = 12 * rg;
        const int mmMax = (rg == 5) ? 14 : 22;      // rg5 covers rows 30,31 only

        u64 acc[6];
        #pragma unroll
        for (int r = 0; r < 6; r++) acc[r] = 0ull;

        #pragma unroll
        for (int mm = 0; mm < 22; mm++) {
            if (mm >= mmMax) break;
            const u64* mrow = (const u64*)((float2*)s_mid + (mbase + mm) * MSTR2 + c);
            u64 md[6];
            #pragma unroll
            for (int s = 0; s < 6; s++) md[s] = mrow[s];

            const int rlo = (mm >= 12) ? ((mm - 10) >> 1) : 0;
            const int rhi = (mm >> 1) < 5 ? (mm >> 1) : 5;
            #pragma unroll
            for (int r = 0; r < 6; r++) {
                if (r < rlo || r > rhi) continue;       // folds at compile time
                const int ky = mm - 2 * r;
                const ulonglong2* fq = (const ulonglong2*)(s_fd + ky * 12);
                ulonglong2 f01 = fq[0], f23 = fq[1], f45 = fq[2];
                acc[r] = ffma2(md[0], f01.x, acc[r]);
                acc[r] = ffma2(md[1], f01.y, acc[r]);
                acc[r] = ffma2(md[2], f23.x, acc[r]);
                acc[r] = ffma2(md[3], f23.y, acc[r]);
                acc[r] = ffma2(md[4], f45.x, acc[r]);
                acc[r] = ffma2(md[5], f45.y, acc[r]);
            }
        }

        const int gx = ox0 + c;
        if (gx < OHW) {
            float* op = out + (size_t)plane * (OHW * OHW) + gx;
            #pragma unroll
            for (int r = 0; r < 6; r++) {
                const int orow = rg * 6 + r;
                const int gy = oy0 + orow;
                if (orow < TY && gy < OHW) {
                    float2 v = unpack2(acc[r]);
                    op[gy * OHW] = v.x + v.y;
                }
            }
        }
    }
}

extern "C" void kernel_launch(void* const* d_in, const int* in_sizes, int n_in,
                              void* d_out, int out_size)
{
    const float* in   = (const float*)d_in[0];
    const float* bias = (const float*)d_in[1];
    const float* fu   = (const float*)d_in[2];
    const float* fd   = (const float*)d_in[3];
    float* out        = (float*)d_out;

    const size_t smem = SMEM_FLOATS * sizeof(float);   // 71200 B
    cudaFuncSetAttribute(afa_fused_kernel,
                         cudaFuncAttributeMaxDynamicSharedMemorySize, (int)smem);

    const int nblocks = 1024 * 8;
    afa_fused_kernel<<<nblocks, NTHREADS, smem>>>(in, bias, fu, fd, out);
}